// round 7
// baseline (speedup 1.0000x reference)
#include <cuda_runtime.h>
#include <cuda_bf16.h>
#include <math.h>
#include <stdint.h>

#define BATCH 4
#define SEQ   4096
#define CDIM  128
#define MTOT  (BATCH*SEQ)
#define KVT   64
#define NTILES (SEQ/KVT)

// bf16 hi/lo split operands (scale folded into Q). V stored TRANSPOSED per batch: [b][c][n].
__device__ __nv_bfloat16 g_Qh[MTOT*CDIM], g_Ql[MTOT*CDIM];
__device__ __nv_bfloat16 g_Kh[MTOT*CDIM], g_Kl[MTOT*CDIM];
__device__ __nv_bfloat16 g_Vth[MTOT*CDIM], g_Vtl[MTOT*CDIM];

// ---------------- warp-MMA helpers (baseline PTX, sm_80+) ----------------
__device__ __forceinline__ uint32_t smem_u32(const void* p) {
    uint32_t a;
    asm("{ .reg .u64 t; cvta.to.shared.u64 t, %1; cvt.u32.u64 %0, t; }" : "=r"(a) : "l"(p));
    return a;
}
#define LDSM_X4(r0, r1, r2, r3, addr) \
    asm volatile("ldmatrix.sync.aligned.m8n8.x4.shared.b16 {%0,%1,%2,%3}, [%4];" \
        : "=r"(r0), "=r"(r1), "=r"(r2), "=r"(r3) : "r"(addr))

// NOTE: not volatile — pure register computation, lets the compiler interleave
// independent MMA chains for ILP.
__device__ __forceinline__ void mma_bf16(float c[4], const uint32_t a[4],
                                         uint32_t b0, uint32_t b1) {
    asm("mma.sync.aligned.m16n8k16.row.col.f32.bf16.bf16.f32 "
        "{%0,%1,%2,%3}, {%4,%5,%6,%7}, {%8,%9}, {%0,%1,%2,%3};"
        : "+f"(c[0]), "+f"(c[1]), "+f"(c[2]), "+f"(c[3])
        : "r"(a[0]), "r"(a[1]), "r"(a[2]), "r"(a[3]), "r"(b0), "r"(b1));
}

// bf16 split helpers
__device__ __forceinline__ uint32_t pack_hi2(float a, float b, float& ra, float& rb) {
    __nv_bfloat162 h = __floats2bfloat162_rn(a, b);
    ra = a - __bfloat162float(h.x);
    rb = b - __bfloat162float(h.y);
    return *(uint32_t*)&h;
}
__device__ __forceinline__ uint32_t pack2(float a, float b) {
    __nv_bfloat162 h = __floats2bfloat162_rn(a, b);
    return *(uint32_t*)&h;
}

// ---------------------------------------------------------------------------
// Kernel 1: QKV projection -> bf16 hi/lo splits. Q scaled by 1/(sqrt(C)*scale).
// V written transposed per batch: g_Vt[b][c][n]. (fp32 compute, exact)
// ---------------------------------------------------------------------------
__global__ __launch_bounds__(256, 1)
void qkv_kernel(const float* __restrict__ x, const float* __restrict__ Wfc,
                const float* __restrict__ bfc, const float* __restrict__ scale) {
    extern __shared__ float smem[];
    float4* Xs4 = (float4*)smem;               // 64x128 swizzled (2048 f4)
    float4* Ws4 = (float4*)(smem + 8192);      // 128 x 17 f4 (stride-68 floats)

    const int tid = threadIdx.x;
    const int tx = tid & 15, ty = tid >> 4;
    const int m0 = ty * 4, n0 = tx * 4;
    const int mbase = blockIdx.x * 64;
    const int cbase = blockIdx.y * 64;

    const float4* xg = (const float4*)(x + (size_t)mbase * CDIM);
    #pragma unroll
    for (int i = 0; i < 8; i++) {
        int idx = i * 256 + tid;
        int r = idx >> 5, kc = idx & 31;
        Xs4[r * 32 + (kc ^ (r & 31))] = xg[idx];
    }
    #pragma unroll
    for (int i = 0; i < 8; i++) {
        int idx = i * 256 + tid;
        int kr = idx >> 4, nq = idx & 15;
        Ws4[kr * 17 + nq] = ((const float4*)(Wfc + kr * 384 + cbase))[nq];
    }
    __syncthreads();

    float acc[4][4];
    #pragma unroll
    for (int i = 0; i < 4; i++)
        #pragma unroll
        for (int j = 0; j < 4; j++) acc[i][j] = 0.f;

    #pragma unroll 4
    for (int k4 = 0; k4 < 32; k4++) {
        float4 b0 = Ws4[(4 * k4 + 0) * 17 + tx];
        float4 b1 = Ws4[(4 * k4 + 1) * 17 + tx];
        float4 b2 = Ws4[(4 * k4 + 2) * 17 + tx];
        float4 b3 = Ws4[(4 * k4 + 3) * 17 + tx];
        #pragma unroll
        for (int i = 0; i < 4; i++) {
            float4 a = Xs4[(m0 + i) * 32 + (k4 ^ ((m0 + i) & 31))];
            acc[i][0] += a.x * b0.x + a.y * b1.x + a.z * b2.x + a.w * b3.x;
            acc[i][1] += a.x * b0.y + a.y * b1.y + a.z * b2.y + a.w * b3.y;
            acc[i][2] += a.x * b0.z + a.y * b1.z + a.z * b2.z + a.w * b3.z;
            acc[i][3] += a.x * b0.w + a.y * b1.w + a.z * b2.w + a.w * b3.w;
        }
    }

    float4 bias = *(const float4*)(bfc + cbase + n0);
    const int sel = blockIdx.y >> 1;            // 0=Q, 1=K, 2=V

    if (sel < 2) {
        float mul = 1.0f;
        if (sel == 0) mul = 1.0f / (sqrtf((float)CDIM) * scale[0]);
        __nv_bfloat16* bh = sel ? g_Kh : g_Qh;
        __nv_bfloat16* bl = sel ? g_Kl : g_Ql;
        const int lc = ((blockIdx.y & 1) << 6) + n0;
        #pragma unroll
        for (int i = 0; i < 4; i++) {
            float v0 = (acc[i][0] + bias.x) * mul;
            float v1 = (acc[i][1] + bias.y) * mul;
            float v2 = (acc[i][2] + bias.z) * mul;
            float v3 = (acc[i][3] + bias.w) * mul;
            float r0, r1, r2, r3;
            uint32_t h01 = pack_hi2(v0, v1, r0, r1);
            uint32_t h23 = pack_hi2(v2, v3, r2, r3);
            uint32_t l01 = pack2(r0, r1);
            uint32_t l23 = pack2(r2, r3);
            size_t off = (size_t)(mbase + m0 + i) * CDIM + lc;
            *(uint2*)(bh + off) = make_uint2(h01, h23);
            *(uint2*)(bl + off) = make_uint2(l01, l23);
        }
    } else {
        // transpose via SMEM, then coalesced bf16-split stores to g_Vt[b][c][n]
        __syncthreads();
        float* T = smem;                        // 64 x 65
        #pragma unroll
        for (int i = 0; i < 4; i++) {
            T[(m0 + i) * 65 + n0 + 0] = acc[i][0] + bias.x;
            T[(m0 + i) * 65 + n0 + 1] = acc[i][1] + bias.y;
            T[(m0 + i) * 65 + n0 + 2] = acc[i][2] + bias.z;
            T[(m0 + i) * 65 + n0 + 3] = acc[i][3] + bias.w;
        }
        __syncthreads();
        const int c_local = tid & 63, seg = tid >> 6;
        const int cg = ((blockIdx.y & 1) << 6) + c_local;
        const int bb = mbase >> 12;
        size_t basea = ((size_t)(bb * CDIM + cg)) * SEQ + (mbase & 4095) + seg * 16;
        uint32_t hw[8], lw[8];
        #pragma unroll
        for (int u = 0; u < 8; u++) {
            float v0 = T[(seg * 16 + 2 * u) * 65 + c_local];
            float v1 = T[(seg * 16 + 2 * u + 1) * 65 + c_local];
            float r0, r1;
            hw[u] = pack_hi2(v0, v1, r0, r1);
            lw[u] = pack2(r0, r1);
        }
        *(uint4*)(g_Vth + basea)     = make_uint4(hw[0], hw[1], hw[2], hw[3]);
        *(uint4*)(g_Vth + basea + 8) = make_uint4(hw[4], hw[5], hw[6], hw[7]);
        *(uint4*)(g_Vtl + basea)     = make_uint4(lw[0], lw[1], lw[2], lw[3]);
        *(uint4*)(g_Vtl + basea + 8) = make_uint4(lw[4], lw[5], lw[6], lw[7]);
    }
}

// ---------------------------------------------------------------------------
// Kernel 2: warp-MMA (HMMA) flash attention + fused output projection.
// Grid (64, 4) = 256 CTAs, block 128 threads = 4 warps -> 2 CTAs/SM for
// cross-CTA latency hiding. Warp w owns Q rows [w*16, w*16+16) of a 64-row tile.
// Q in registers; S->P->PV in registers. 3-chain bf16 splits throughout.
// SMEM: Kh[64x136], Kl, Vth[128x72], Vtl = 70KB (2 CTAs = 140KB/SM).
// ---------------------------------------------------------------------------
#define QSTR 136   // bf16 stride (272B): conflict-free ldmatrix
#define VSTR 72    // bf16 stride (144B) for Vt tiles
#define OFF_KH 0
#define OFF_KL 17408
#define OFF_VH 34816
#define OFF_VL 53248
#define SM_TOT 71680

__global__ __launch_bounds__(128, 2)
void attn_kernel(const float* __restrict__ Wout, const float* __restrict__ bout,
                 float* __restrict__ out) {
    extern __shared__ char smem8[];
    const uint32_t sb = smem_u32(smem8);
    const int tid = threadIdx.x, lane = tid & 31, w = tid >> 5;
    const int b = blockIdx.y;
    const int qr0 = blockIdx.x * 64;

    // B-fragment lane addressing (ldmatrix.x4 over a 16-row n-pair)
    const int bn  = (lane & 7) | ((lane & 16) >> 1);   // n row within 16
    const int bk8 = (lane & 8);                         // +8 k offset
    // A-fragment lane addressing
    const int ar  = lane & 15;
    const int ac8 = (lane >> 4) << 3;

    // ---- stage Qh then Ql through SMEM (reuses K region), load A fragments ----
    // Q tile = 64 rows x 128 cols bf16 = 1024 uint4 -> 8 iterations of 128 threads.
    uint32_t qh[8][4], ql[8][4];
    {
        __nv_bfloat16* Qs = (__nv_bfloat16*)smem8;
        #pragma unroll
        for (int i = 0; i < 8; i++) {
            int idx = i * 128 + tid;
            int r = idx >> 4, c = (idx & 15) << 3;
            *(uint4*)(Qs + r * QSTR + c) =
                *(const uint4*)(g_Qh + (size_t)(b * SEQ + qr0 + r) * CDIM + c);
        }
        __syncthreads();
        #pragma unroll
        for (int kk = 0; kk < 8; kk++) {
            uint32_t a = sb + ((w * 16 + ar) * QSTR + kk * 16 + ac8) * 2;
            LDSM_X4(qh[kk][0], qh[kk][1], qh[kk][2], qh[kk][3], a);
        }
        __syncthreads();
        #pragma unroll
        for (int i = 0; i < 8; i++) {
            int idx = i * 128 + tid;
            int r = idx >> 4, c = (idx & 15) << 3;
            *(uint4*)(Qs + r * QSTR + c) =
                *(const uint4*)(g_Ql + (size_t)(b * SEQ + qr0 + r) * CDIM + c);
        }
        __syncthreads();
        #pragma unroll
        for (int kk = 0; kk < 8; kk++) {
            uint32_t a = sb + ((w * 16 + ar) * QSTR + kk * 16 + ac8) * 2;
            LDSM_X4(ql[kk][0], ql[kk][1], ql[kk][2], ql[kk][3], a);
        }
    }

    float co[16][4];
    #pragma unroll
    for (int i = 0; i < 16; i++)
        #pragma unroll
        for (int j = 0; j < 4; j++) co[i][j] = 0.f;
    float l0 = 0.f, l1 = 0.f;

    for (int t = 0; t < NTILES; t++) {
        const int kr0 = t * KVT;
        __syncthreads();   // previous tile's SMEM reads complete
        // K tiles: 64 rows x 128 bf16 (hi & lo) = 1024 uint4 each
        #pragma unroll
        for (int i = 0; i < 8; i++) {
            int idx = i * 128 + tid;
            int r = idx >> 4, c = (idx & 15) << 3;
            size_t g = (size_t)(b * SEQ + kr0 + r) * CDIM + c;
            *(uint4*)(smem8 + OFF_KH + r * (QSTR * 2) + c * 2) = *(const uint4*)(g_Kh + g);
            *(uint4*)(smem8 + OFF_KL + r * (QSTR * 2) + c * 2) = *(const uint4*)(g_Kl + g);
        }
        // Vt tiles: 128 rows (c) x 64 bf16 (kv) = 1024 uint4 each
        #pragma unroll
        for (int i = 0; i < 8; i++) {
            int idx = i * 128 + tid;
            int r = idx >> 3, j8 = (idx & 7) << 3;
            size_t g = (size_t)(b * CDIM + r) * SEQ + kr0 + j8;
            *(uint4*)(smem8 + OFF_VH + r * (VSTR * 2) + j8 * 2) = *(const uint4*)(g_Vth + g);
            *(uint4*)(smem8 + OFF_VL + r * (VSTR * 2) + j8 * 2) = *(const uint4*)(g_Vtl + g);
        }
        __syncthreads();

        // ---- S = Q.K^T (3 chains) ----
        float cs[8][4];
        #pragma unroll
        for (int i = 0; i < 8; i++)
            #pragma unroll
            for (int j = 0; j < 4; j++) cs[i][j] = 0.f;

        #pragma unroll
        for (int kk = 0; kk < 8; kk++) {
            #pragma unroll
            for (int nbp = 0; nbp < 4; nbp++) {
                uint32_t off = ((nbp * 16 + bn) * (QSTR * 2)) + (kk * 16 + bk8) * 2;
                uint32_t h0, h1, h2, h3, l0r, l1r, l2r, l3r;
                LDSM_X4(h0, h1, h2, h3, sb + OFF_KH + off);
                LDSM_X4(l0r, l1r, l2r, l3r, sb + OFF_KL + off);
                mma_bf16(cs[2 * nbp],     qh[kk], h0, h1);
                mma_bf16(cs[2 * nbp + 1], qh[kk], h2, h3);
                mma_bf16(cs[2 * nbp],     qh[kk], l0r, l1r);
                mma_bf16(cs[2 * nbp + 1], qh[kk], l2r, l3r);
                mma_bf16(cs[2 * nbp],     ql[kk], h0, h1);
                mma_bf16(cs[2 * nbp + 1], ql[kk], h2, h3);
            }
        }

        // ---- P = exp(S); accumulate l; pack into A fragments (hi/lo) ----
        uint32_t pah[4][4], pal[4][4];
        #pragma unroll
        for (int nb = 0; nb < 8; nb++) {
            cs[nb][0] = __expf(cs[nb][0]);
            cs[nb][1] = __expf(cs[nb][1]);
            cs[nb][2] = __expf(cs[nb][2]);
            cs[nb][3] = __expf(cs[nb][3]);
            l0 += cs[nb][0] + cs[nb][1];
            l1 += cs[nb][2] + cs[nb][3];
        }
        #pragma unroll
        for (int j = 0; j < 4; j++) {
            float r0, r1;
            pah[j][0] = pack_hi2(cs[2*j][0],   cs[2*j][1],   r0, r1); pal[j][0] = pack2(r0, r1);
            pah[j][1] = pack_hi2(cs[2*j][2],   cs[2*j][3],   r0, r1); pal[j][1] = pack2(r0, r1);
            pah[j][2] = pack_hi2(cs[2*j+1][0], cs[2*j+1][1], r0, r1); pal[j][2] = pack2(r0, r1);
            pah[j][3] = pack_hi2(cs[2*j+1][2], cs[2*j+1][3], r0, r1); pal[j][3] = pack2(r0, r1);
        }

        // ---- O += P.V (3 chains) ----
        #pragma unroll
        for (int kk = 0; kk < 4; kk++) {
            #pragma unroll
            for (int nbp = 0; nbp < 8; nbp++) {
                uint32_t off = ((nbp * 16 + bn) * (VSTR * 2)) + (kk * 16 + bk8) * 2;
                uint32_t h0, h1, h2, h3, l0r, l1r, l2r, l3r;
                LDSM_X4(h0, h1, h2, h3, sb + OFF_VH + off);
                LDSM_X4(l0r, l1r, l2r, l3r, sb + OFF_VL + off);
                mma_bf16(co[2 * nbp],     pah[kk], h0, h1);
                mma_bf16(co[2 * nbp + 1], pah[kk], h2, h3);
                mma_bf16(co[2 * nbp],     pah[kk], l0r, l1r);
                mma_bf16(co[2 * nbp + 1], pah[kk], l2r, l3r);
                mma_bf16(co[2 * nbp],     pal[kk], h0, h1);
                mma_bf16(co[2 * nbp + 1], pal[kk], h2, h3);
            }
        }
    }

    // ---- finalize l (4 lanes share each row), normalize O ----
    l0 += __shfl_xor_sync(0xffffffffu, l0, 1);
    l0 += __shfl_xor_sync(0xffffffffu, l0, 2);
    l1 += __shfl_xor_sync(0xffffffffu, l1, 1);
    l1 += __shfl_xor_sync(0xffffffffu, l1, 2);
    const float inv0 = 1.0f / l0, inv1 = 1.0f / l1;
    #pragma unroll
    for (int nb = 0; nb < 16; nb++) {
        co[nb][0] *= inv0; co[nb][1] *= inv0;
        co[nb][2] *= inv1; co[nb][3] *= inv1;
    }

    // ---- W_out^T hi/lo -> SMEM (reuse) ----
    __syncthreads();
    {
        __nv_bfloat16* Wh = (__nv_bfloat16*)smem8;             // 128 x QSTR
        __nv_bfloat16* Wl = (__nv_bfloat16*)(smem8 + OFF_VH);  // 128 x QSTR
        for (int idx = tid; idx < CDIM * CDIM; idx += 128) {
            int cin = idx >> 7, cout = idx & 127;
            float wv = Wout[idx];
            __nv_bfloat16 hh = __float2bfloat16(wv);
            __nv_bfloat16 ll = __float2bfloat16(wv - __bfloat162float(hh));
            Wh[cout * QSTR + cin] = hh;
            Wl[cout * QSTR + cin] = ll;
        }
    }

    // ---- O -> A fragments (hi/lo) ----
    uint32_t oah[8][4], oal[8][4];
    #pragma unroll
    for (int j = 0; j < 8; j++) {
        float r0, r1;
        oah[j][0] = pack_hi2(co[2*j][0],   co[2*j][1],   r0, r1); oal[j][0] = pack2(r0, r1);
        oah[j][1] = pack_hi2(co[2*j][2],   co[2*j][3],   r0, r1); oal[j][1] = pack2(r0, r1);
        oah[j][2] = pack_hi2(co[2*j+1][0], co[2*j+1][1], r0, r1); oal[j][2] = pack2(r0, r1);
        oah[j][3] = pack_hi2(co[2*j+1][2], co[2*j+1][3], r0, r1); oal[j][3] = pack2(r0, r1);
    }
    __syncthreads();

    // ---- D = O @ W_out (3 chains), accumulate into co (reused) ----
    #pragma unroll
    for (int i = 0; i < 16; i++)
        #pragma unroll
        for (int j = 0; j < 4; j++) co[i][j] = 0.f;

    #pragma unroll
    for (int kk = 0; kk < 8; kk++) {
        #pragma unroll
        for (int nbp = 0; nbp < 8; nbp++) {
            uint32_t off = ((nbp * 16 + bn) * (QSTR * 2)) + (kk * 16 + bk8) * 2;
            uint32_t h0, h1, h2, h3, l0r, l1r, l2r, l3r;
            LDSM_X4(h0, h1, h2, h3, sb + off);
            LDSM_X4(l0r, l1r, l2r, l3r, sb + OFF_VH + off);
            mma_bf16(co[2 * nbp],     oah[kk], h0, h1);
            mma_bf16(co[2 * nbp + 1], oah[kk], h2, h3);
            mma_bf16(co[2 * nbp],     oah[kk], l0r, l1r);
            mma_bf16(co[2 * nbp + 1], oah[kk], l2r, l3r);
            mma_bf16(co[2 * nbp],     oal[kk], h0, h1);
            mma_bf16(co[2 * nbp + 1], oal[kk], h2, h3);
        }
    }

    // ---- + bias, store ----
    {
        const int r0g = qr0 + w * 16 + (lane >> 2);
        const int cb = (lane & 3) * 2;
        float* base0 = out + (size_t)(b * SEQ + r0g) * CDIM;
        float* base1 = base0 + 8 * CDIM;
        #pragma unroll
        for (int nb = 0; nb < 16; nb++) {
            int col = nb * 8 + cb;
            float bx = bout[col], by = bout[col + 1];
            float2 v0 = make_float2(co[nb][0] + bx, co[nb][1] + by);
            float2 v1 = make_float2(co[nb][2] + bx, co[nb][3] + by);
            *(float2*)(base0 + col) = v0;
            *(float2*)(base1 + col) = v1;
        }
    }
}

// ---------------------------------------------------------------------------
extern "C" void kernel_launch(void* const* d_in, const int* in_sizes, int n_in,
                              void* d_out, int out_size) {
    const float* x    = (const float*)d_in[0];
    const float* Wfc  = (const float*)d_in[1];
    const float* bfc  = (const float*)d_in[2];
    const float* Wout = (const float*)d_in[3];
    const float* bo   = (const float*)d_in[4];
    const float* sc   = (const float*)d_in[5];
    float* out = (float*)d_out;

    const int smem1 = (8192 + 128 * 68) * 4;   // 67584 B
    cudaFuncSetAttribute(qkv_kernel, cudaFuncAttributeMaxDynamicSharedMemorySize, smem1);
    cudaFuncSetAttribute(attn_kernel, cudaFuncAttributeMaxDynamicSharedMemorySize, SM_TOT);

    qkv_kernel<<<dim3(256, 6), 256, smem1>>>(x, Wfc, bfc, sc);
    attn_kernel<<<dim3(64, 4), 128, SM_TOT>>>(Wout, bo, out);
}

// round 8
// speedup vs baseline: 1.0976x; 1.0976x over previous
#include <cuda_runtime.h>
#include <cuda_bf16.h>
#include <math.h>
#include <stdint.h>

#define BATCH 4
#define SEQ   4096
#define CDIM  128
#define MTOT  (BATCH*SEQ)
#define KVT   64
#define NTILES (SEQ/KVT)

// bf16 hi/lo split operands (scale folded into Q). V stored TRANSPOSED per batch: [b][c][n].
__device__ __nv_bfloat16 g_Qh[MTOT*CDIM], g_Ql[MTOT*CDIM];
__device__ __nv_bfloat16 g_Kh[MTOT*CDIM], g_Kl[MTOT*CDIM];
__device__ __nv_bfloat16 g_Vth[MTOT*CDIM], g_Vtl[MTOT*CDIM];

// ---------------- warp-MMA helpers (baseline PTX, sm_80+) ----------------
__device__ __forceinline__ uint32_t smem_u32(const void* p) {
    uint32_t a;
    asm("{ .reg .u64 t; cvta.to.shared.u64 t, %1; cvt.u32.u64 %0, t; }" : "=r"(a) : "l"(p));
    return a;
}
#define LDSM_X4(r0, r1, r2, r3, addr) \
    asm volatile("ldmatrix.sync.aligned.m8n8.x4.shared.b16 {%0,%1,%2,%3}, [%4];" \
        : "=r"(r0), "=r"(r1), "=r"(r2), "=r"(r3) : "r"(addr))

// not volatile — pure register computation, lets the compiler interleave chains.
__device__ __forceinline__ void mma_bf16(float c[4], const uint32_t a[4],
                                         uint32_t b0, uint32_t b1) {
    asm("mma.sync.aligned.m16n8k16.row.col.f32.bf16.bf16.f32 "
        "{%0,%1,%2,%3}, {%4,%5,%6,%7}, {%8,%9}, {%0,%1,%2,%3};"
        : "+f"(c[0]), "+f"(c[1]), "+f"(c[2]), "+f"(c[3])
        : "r"(a[0]), "r"(a[1]), "r"(a[2]), "r"(a[3]), "r"(b0), "r"(b1));
}

#define CP_ASYNC16(dst_u32, src_ptr) \
    asm volatile("cp.async.cg.shared.global [%0], [%1], 16;" \
        :: "r"(dst_u32), "l"(src_ptr) : "memory")
#define CP_COMMIT() asm volatile("cp.async.commit_group;" ::: "memory")
#define CP_WAIT0()  asm volatile("cp.async.wait_group 0;" ::: "memory")

// bf16 split helpers
__device__ __forceinline__ uint32_t pack_hi2(float a, float b, float& ra, float& rb) {
    __nv_bfloat162 h = __floats2bfloat162_rn(a, b);
    ra = a - __bfloat162float(h.x);
    rb = b - __bfloat162float(h.y);
    return *(uint32_t*)&h;
}
__device__ __forceinline__ uint32_t pack2(float a, float b) {
    __nv_bfloat162 h = __floats2bfloat162_rn(a, b);
    return *(uint32_t*)&h;
}

// ---------------------------------------------------------------------------
// Kernel 1: QKV projection -> bf16 hi/lo splits. Q scaled by 1/(sqrt(C)*scale).
// V written transposed per batch: g_Vt[b][c][n]. (fp32 compute, exact)
// ---------------------------------------------------------------------------
__global__ __launch_bounds__(256, 1)
void qkv_kernel(const float* __restrict__ x, const float* __restrict__ Wfc,
                const float* __restrict__ bfc, const float* __restrict__ scale) {
    extern __shared__ float smem[];
    float4* Xs4 = (float4*)smem;               // 64x128 swizzled (2048 f4)
    float4* Ws4 = (float4*)(smem + 8192);      // 128 x 17 f4 (stride-68 floats)

    const int tid = threadIdx.x;
    const int tx = tid & 15, ty = tid >> 4;
    const int m0 = ty * 4, n0 = tx * 4;
    const int mbase = blockIdx.x * 64;
    const int cbase = blockIdx.y * 64;

    const float4* xg = (const float4*)(x + (size_t)mbase * CDIM);
    #pragma unroll
    for (int i = 0; i < 8; i++) {
        int idx = i * 256 + tid;
        int r = idx >> 5, kc = idx & 31;
        Xs4[r * 32 + (kc ^ (r & 31))] = xg[idx];
    }
    #pragma unroll
    for (int i = 0; i < 8; i++) {
        int idx = i * 256 + tid;
        int kr = idx >> 4, nq = idx & 15;
        Ws4[kr * 17 + nq] = ((const float4*)(Wfc + kr * 384 + cbase))[nq];
    }
    __syncthreads();

    float acc[4][4];
    #pragma unroll
    for (int i = 0; i < 4; i++)
        #pragma unroll
        for (int j = 0; j < 4; j++) acc[i][j] = 0.f;

    #pragma unroll 4
    for (int k4 = 0; k4 < 32; k4++) {
        float4 b0 = Ws4[(4 * k4 + 0) * 17 + tx];
        float4 b1 = Ws4[(4 * k4 + 1) * 17 + tx];
        float4 b2 = Ws4[(4 * k4 + 2) * 17 + tx];
        float4 b3 = Ws4[(4 * k4 + 3) * 17 + tx];
        #pragma unroll
        for (int i = 0; i < 4; i++) {
            float4 a = Xs4[(m0 + i) * 32 + (k4 ^ ((m0 + i) & 31))];
            acc[i][0] += a.x * b0.x + a.y * b1.x + a.z * b2.x + a.w * b3.x;
            acc[i][1] += a.x * b0.y + a.y * b1.y + a.z * b2.y + a.w * b3.y;
            acc[i][2] += a.x * b0.z + a.y * b1.z + a.z * b2.z + a.w * b3.z;
            acc[i][3] += a.x * b0.w + a.y * b1.w + a.z * b2.w + a.w * b3.w;
        }
    }

    float4 bias = *(const float4*)(bfc + cbase + n0);
    const int sel = blockIdx.y >> 1;            // 0=Q, 1=K, 2=V

    if (sel < 2) {
        float mul = 1.0f;
        if (sel == 0) mul = 1.0f / (sqrtf((float)CDIM) * scale[0]);
        __nv_bfloat16* bh = sel ? g_Kh : g_Qh;
        __nv_bfloat16* bl = sel ? g_Kl : g_Ql;
        const int lc = ((blockIdx.y & 1) << 6) + n0;
        #pragma unroll
        for (int i = 0; i < 4; i++) {
            float v0 = (acc[i][0] + bias.x) * mul;
            float v1 = (acc[i][1] + bias.y) * mul;
            float v2 = (acc[i][2] + bias.z) * mul;
            float v3 = (acc[i][3] + bias.w) * mul;
            float r0, r1, r2, r3;
            uint32_t h01 = pack_hi2(v0, v1, r0, r1);
            uint32_t h23 = pack_hi2(v2, v3, r2, r3);
            uint32_t l01 = pack2(r0, r1);
            uint32_t l23 = pack2(r2, r3);
            size_t off = (size_t)(mbase + m0 + i) * CDIM + lc;
            *(uint2*)(bh + off) = make_uint2(h01, h23);
            *(uint2*)(bl + off) = make_uint2(l01, l23);
        }
    } else {
        // transpose via SMEM, then coalesced bf16-split stores to g_Vt[b][c][n]
        __syncthreads();
        float* T = smem;                        // 64 x 65
        #pragma unroll
        for (int i = 0; i < 4; i++) {
            T[(m0 + i) * 65 + n0 + 0] = acc[i][0] + bias.x;
            T[(m0 + i) * 65 + n0 + 1] = acc[i][1] + bias.y;
            T[(m0 + i) * 65 + n0 + 2] = acc[i][2] + bias.z;
            T[(m0 + i) * 65 + n0 + 3] = acc[i][3] + bias.w;
        }
        __syncthreads();
        const int c_local = tid & 63, seg = tid >> 6;
        const int cg = ((blockIdx.y & 1) << 6) + c_local;
        const int bb = mbase >> 12;
        size_t basea = ((size_t)(bb * CDIM + cg)) * SEQ + (mbase & 4095) + seg * 16;
        uint32_t hw[8], lw[8];
        #pragma unroll
        for (int u = 0; u < 8; u++) {
            float v0 = T[(seg * 16 + 2 * u) * 65 + c_local];
            float v1 = T[(seg * 16 + 2 * u + 1) * 65 + c_local];
            float r0, r1;
            hw[u] = pack_hi2(v0, v1, r0, r1);
            lw[u] = pack2(r0, r1);
        }
        *(uint4*)(g_Vth + basea)     = make_uint4(hw[0], hw[1], hw[2], hw[3]);
        *(uint4*)(g_Vth + basea + 8) = make_uint4(hw[4], hw[5], hw[6], hw[7]);
        *(uint4*)(g_Vtl + basea)     = make_uint4(lw[0], lw[1], lw[2], lw[3]);
        *(uint4*)(g_Vtl + basea + 8) = make_uint4(lw[4], lw[5], lw[6], lw[7]);
    }
}

// ---------------------------------------------------------------------------
// Kernel 2: warp-MMA (HMMA) flash attention + fused output projection.
// Grid (32, 4) = 128 CTAs (one clean wave), 256 threads = 8 warps.
// cp.async double-buffered K/V (2 x 70KB): prefetch tile t+1 during tile t MMAs.
// Warp w owns Q rows [w*16, w*16+16). 3-chain bf16 splits throughout.
// ---------------------------------------------------------------------------
#define QSTR 136   // bf16 stride (272B): conflict-free ldmatrix
#define VSTR 72    // bf16 stride (144B) for Vt tiles
#define OFF_KH 0
#define OFF_KL 17408
#define OFF_VH 34816
#define OFF_VL 53248
#define BUFSZ  71680
#define SM_TOT (2*BUFSZ)   // 143360

__device__ __forceinline__ void prefetch_tile(uint32_t sbuf, int b, int kr0, int tid) {
    // K tiles: 64 rows x 128 bf16 (hi & lo) = 1024 uint4 each
    #pragma unroll
    for (int i = 0; i < 4; i++) {
        int idx = i * 256 + tid;
        int r = idx >> 4, c = (idx & 15) << 3;
        size_t g = (size_t)(b * SEQ + kr0 + r) * CDIM + c;
        CP_ASYNC16(sbuf + OFF_KH + r * (QSTR * 2) + c * 2, g_Kh + g);
        CP_ASYNC16(sbuf + OFF_KL + r * (QSTR * 2) + c * 2, g_Kl + g);
    }
    // Vt tiles: 128 rows (c) x 64 bf16 (kv) = 1024 uint4 each
    #pragma unroll
    for (int i = 0; i < 4; i++) {
        int idx = i * 256 + tid;
        int r = idx >> 3, j8 = (idx & 7) << 3;
        size_t g = (size_t)(b * CDIM + r) * SEQ + kr0 + j8;
        CP_ASYNC16(sbuf + OFF_VH + r * (VSTR * 2) + j8 * 2, g_Vth + g);
        CP_ASYNC16(sbuf + OFF_VL + r * (VSTR * 2) + j8 * 2, g_Vtl + g);
    }
    CP_COMMIT();
}

__global__ __launch_bounds__(256, 1)
void attn_kernel(const float* __restrict__ Wout, const float* __restrict__ bout,
                 float* __restrict__ out) {
    extern __shared__ char smem8[];
    const uint32_t sb = smem_u32(smem8);
    const int tid = threadIdx.x, lane = tid & 31, w = tid >> 5;
    const int b = blockIdx.y;
    const int qr0 = blockIdx.x * 128;

    // B-fragment lane addressing (ldmatrix.x4 over a 16-row n-pair)
    const int bn  = (lane & 7) | ((lane & 16) >> 1);   // n row within 16
    const int bk8 = (lane & 8);                         // +8 k offset
    // A-fragment lane addressing
    const int ar  = lane & 15;
    const int ac8 = (lane >> 4) << 3;

    // ---- kick off prefetch of tile 0 into buffer 0 ----
    prefetch_tile(sb, b, 0, tid);

    // ---- stage Qh then Ql through buffer-1 region, load A fragments ----
    // Q tile = 128 rows x 128 cols bf16 = 2048 uint4 -> 8 iters of 256 threads.
    uint32_t qh[8][4], ql[8][4];
    {
        __nv_bfloat16* Qs = (__nv_bfloat16*)(smem8 + BUFSZ);
        const uint32_t qsb = sb + BUFSZ;
        #pragma unroll
        for (int i = 0; i < 8; i++) {
            int idx = i * 256 + tid;
            int r = idx >> 4, c = (idx & 15) << 3;
            *(uint4*)(Qs + r * QSTR + c) =
                *(const uint4*)(g_Qh + (size_t)(b * SEQ + qr0 + r) * CDIM + c);
        }
        __syncthreads();
        #pragma unroll
        for (int kk = 0; kk < 8; kk++) {
            uint32_t a = qsb + ((w * 16 + ar) * QSTR + kk * 16 + ac8) * 2;
            LDSM_X4(qh[kk][0], qh[kk][1], qh[kk][2], qh[kk][3], a);
        }
        __syncthreads();
        #pragma unroll
        for (int i = 0; i < 8; i++) {
            int idx = i * 256 + tid;
            int r = idx >> 4, c = (idx & 15) << 3;
            *(uint4*)(Qs + r * QSTR + c) =
                *(const uint4*)(g_Ql + (size_t)(b * SEQ + qr0 + r) * CDIM + c);
        }
        __syncthreads();
        #pragma unroll
        for (int kk = 0; kk < 8; kk++) {
            uint32_t a = qsb + ((w * 16 + ar) * QSTR + kk * 16 + ac8) * 2;
            LDSM_X4(ql[kk][0], ql[kk][1], ql[kk][2], ql[kk][3], a);
        }
    }

    float co[16][4];
    #pragma unroll
    for (int i = 0; i < 16; i++)
        #pragma unroll
        for (int j = 0; j < 4; j++) co[i][j] = 0.f;
    float l0 = 0.f, l1 = 0.f;

    // tile-0 data must be in place before the loop reads buffer 0
    CP_WAIT0();
    __syncthreads();

    for (int t = 0; t < NTILES; t++) {
        const uint32_t sbuf = sb + (t & 1) * BUFSZ;

        // ---- prefetch tile t+1 into the other buffer (consumed @ t-1, free) ----
        if (t + 1 < NTILES)
            prefetch_tile(sb + ((t + 1) & 1) * BUFSZ, b, (t + 1) * KVT, tid);

        // ---- S = Q.K^T (3 chains) ----
        float cs[8][4];
        #pragma unroll
        for (int i = 0; i < 8; i++)
            #pragma unroll
            for (int j = 0; j < 4; j++) cs[i][j] = 0.f;

        #pragma unroll
        for (int kk = 0; kk < 8; kk++) {
            #pragma unroll
            for (int nbp = 0; nbp < 4; nbp++) {
                uint32_t off = ((nbp * 16 + bn) * (QSTR * 2)) + (kk * 16 + bk8) * 2;
                uint32_t h0, h1, h2, h3, l0r, l1r, l2r, l3r;
                LDSM_X4(h0, h1, h2, h3, sbuf + OFF_KH + off);
                LDSM_X4(l0r, l1r, l2r, l3r, sbuf + OFF_KL + off);
                mma_bf16(cs[2 * nbp],     qh[kk], h0, h1);
                mma_bf16(cs[2 * nbp + 1], qh[kk], h2, h3);
                mma_bf16(cs[2 * nbp],     qh[kk], l0r, l1r);
                mma_bf16(cs[2 * nbp + 1], qh[kk], l2r, l3r);
                mma_bf16(cs[2 * nbp],     ql[kk], h0, h1);
                mma_bf16(cs[2 * nbp + 1], ql[kk], h2, h3);
            }
        }

        // ---- P = exp(S); accumulate l; pack into A fragments (hi/lo) ----
        uint32_t pah[4][4], pal[4][4];
        #pragma unroll
        for (int nb = 0; nb < 8; nb++) {
            cs[nb][0] = __expf(cs[nb][0]);
            cs[nb][1] = __expf(cs[nb][1]);
            cs[nb][2] = __expf(cs[nb][2]);
            cs[nb][3] = __expf(cs[nb][3]);
            l0 += cs[nb][0] + cs[nb][1];
            l1 += cs[nb][2] + cs[nb][3];
        }
        #pragma unroll
        for (int j = 0; j < 4; j++) {
            float r0, r1;
            pah[j][0] = pack_hi2(cs[2*j][0],   cs[2*j][1],   r0, r1); pal[j][0] = pack2(r0, r1);
            pah[j][1] = pack_hi2(cs[2*j][2],   cs[2*j][3],   r0, r1); pal[j][1] = pack2(r0, r1);
            pah[j][2] = pack_hi2(cs[2*j+1][0], cs[2*j+1][1], r0, r1); pal[j][2] = pack2(r0, r1);
            pah[j][3] = pack_hi2(cs[2*j+1][2], cs[2*j+1][3], r0, r1); pal[j][3] = pack2(r0, r1);
        }

        // ---- O += P.V (3 chains) ----
        #pragma unroll
        for (int kk = 0; kk < 4; kk++) {
            #pragma unroll
            for (int nbp = 0; nbp < 8; nbp++) {
                uint32_t off = ((nbp * 16 + bn) * (VSTR * 2)) + (kk * 16 + bk8) * 2;
                uint32_t h0, h1, h2, h3, l0r, l1r, l2r, l3r;
                LDSM_X4(h0, h1, h2, h3, sbuf + OFF_VH + off);
                LDSM_X4(l0r, l1r, l2r, l3r, sbuf + OFF_VL + off);
                mma_bf16(co[2 * nbp],     pah[kk], h0, h1);
                mma_bf16(co[2 * nbp + 1], pah[kk], h2, h3);
                mma_bf16(co[2 * nbp],     pah[kk], l0r, l1r);
                mma_bf16(co[2 * nbp + 1], pah[kk], l2r, l3r);
                mma_bf16(co[2 * nbp],     pal[kk], h0, h1);
                mma_bf16(co[2 * nbp + 1], pal[kk], h2, h3);
            }
        }

        // ---- wait for prefetch; all warps done reading before next overwrite ----
        CP_WAIT0();
        __syncthreads();
    }

    // ---- finalize l (4 lanes share each row), normalize O ----
    l0 += __shfl_xor_sync(0xffffffffu, l0, 1);
    l0 += __shfl_xor_sync(0xffffffffu, l0, 2);
    l1 += __shfl_xor_sync(0xffffffffu, l1, 1);
    l1 += __shfl_xor_sync(0xffffffffu, l1, 2);
    const float inv0 = 1.0f / l0, inv1 = 1.0f / l1;
    #pragma unroll
    for (int nb = 0; nb < 16; nb++) {
        co[nb][0] *= inv0; co[nb][1] *= inv0;
        co[nb][2] *= inv1; co[nb][3] *= inv1;
    }

    // ---- W_out^T hi/lo -> SMEM (reuse buffer 0) ----
    {
        __nv_bfloat16* Wh = (__nv_bfloat16*)smem8;             // 128 x QSTR
        __nv_bfloat16* Wl = (__nv_bfloat16*)(smem8 + OFF_VH);  // 128 x QSTR
        for (int idx = tid; idx < CDIM * CDIM; idx += 256) {
            int cin = idx >> 7, cout = idx & 127;
            float wv = Wout[idx];
            __nv_bfloat16 hh = __float2bfloat16(wv);
            __nv_bfloat16 ll = __float2bfloat16(wv - __bfloat162float(hh));
            Wh[cout * QSTR + cin] = hh;
            Wl[cout * QSTR + cin] = ll;
        }
    }

    // ---- O -> A fragments (hi/lo) ----
    uint32_t oah[8][4], oal[8][4];
    #pragma unroll
    for (int j = 0; j < 8; j++) {
        float r0, r1;
        oah[j][0] = pack_hi2(co[2*j][0],   co[2*j][1],   r0, r1); oal[j][0] = pack2(r0, r1);
        oah[j][1] = pack_hi2(co[2*j][2],   co[2*j][3],   r0, r1); oal[j][1] = pack2(r0, r1);
        oah[j][2] = pack_hi2(co[2*j+1][0], co[2*j+1][1], r0, r1); oal[j][2] = pack2(r0, r1);
        oah[j][3] = pack_hi2(co[2*j+1][2], co[2*j+1][3], r0, r1); oal[j][3] = pack2(r0, r1);
    }
    __syncthreads();

    // ---- D = O @ W_out (3 chains), accumulate into co (reused) ----
    #pragma unroll
    for (int i = 0; i < 16; i++)
        #pragma unroll
        for (int j = 0; j < 4; j++) co[i][j] = 0.f;

    #pragma unroll
    for (int kk = 0; kk < 8; kk++) {
        #pragma unroll
        for (int nbp = 0; nbp < 8; nbp++) {
            uint32_t off = ((nbp * 16 + bn) * (QSTR * 2)) + (kk * 16 + bk8) * 2;
            uint32_t h0, h1, h2, h3, l0r, l1r, l2r, l3r;
            LDSM_X4(h0, h1, h2, h3, sb + off);
            LDSM_X4(l0r, l1r, l2r, l3r, sb + OFF_VH + off);
            mma_bf16(co[2 * nbp],     oah[kk], h0, h1);
            mma_bf16(co[2 * nbp + 1], oah[kk], h2, h3);
            mma_bf16(co[2 * nbp],     oah[kk], l0r, l1r);
            mma_bf16(co[2 * nbp + 1], oah[kk], l2r, l3r);
            mma_bf16(co[2 * nbp],     oal[kk], h0, h1);
            mma_bf16(co[2 * nbp + 1], oal[kk], h2, h3);
        }
    }

    // ---- + bias, store ----
    {
        const int r0g = qr0 + w * 16 + (lane >> 2);
        const int cb = (lane & 3) * 2;
        float* base0 = out + (size_t)(b * SEQ + r0g) * CDIM;
        float* base1 = base0 + 8 * CDIM;
        #pragma unroll
        for (int nb = 0; nb < 16; nb++) {
            int col = nb * 8 + cb;
            float bx = bout[col], by = bout[col + 1];
            float2 v0 = make_float2(co[nb][0] + bx, co[nb][1] + by);
            float2 v1 = make_float2(co[nb][2] + bx, co[nb][3] + by);
            *(float2*)(base0 + col) = v0;
            *(float2*)(base1 + col) = v1;
        }
    }
}

// ---------------------------------------------------------------------------
extern "C" void kernel_launch(void* const* d_in, const int* in_sizes, int n_in,
                              void* d_out, int out_size) {
    const float* x    = (const float*)d_in[0];
    const float* Wfc  = (const float*)d_in[1];
    const float* bfc  = (const float*)d_in[2];
    const float* Wout = (const float*)d_in[3];
    const float* bo   = (const float*)d_in[4];
    const float* sc   = (const float*)d_in[5];
    float* out = (float*)d_out;

    const int smem1 = (8192 + 128 * 68) * 4;   // 67584 B
    cudaFuncSetAttribute(qkv_kernel, cudaFuncAttributeMaxDynamicSharedMemorySize, smem1);
    cudaFuncSetAttribute(attn_kernel, cudaFuncAttributeMaxDynamicSharedMemorySize, SM_TOT);

    qkv_kernel<<<dim3(256, 6), 256, smem1>>>(x, Wfc, bfc, sc);
    attn_kernel<<<dim3(32, 4), 256, SM_TOT>>>(Wout, bo, out);
}

// round 10
// speedup vs baseline: 1.1603x; 1.0571x over previous
#include <cuda_runtime.h>
#include <cuda_bf16.h>
#include <math.h>
#include <stdint.h>

#define BATCH 4
#define SEQ   4096
#define CDIM  128
#define MTOT  (BATCH*SEQ)
#define KVT   64
#define NTILES (SEQ/KVT)

// bf16 hi/lo split operands (scale folded into Q). V stored TRANSPOSED per batch: [b][c][n].
__device__ __nv_bfloat16 g_Qh[MTOT*CDIM], g_Ql[MTOT*CDIM];
__device__ __nv_bfloat16 g_Kh[MTOT*CDIM], g_Kl[MTOT*CDIM];
__device__ __nv_bfloat16 g_Vth[MTOT*CDIM], g_Vtl[MTOT*CDIM];

// ---------------- warp-MMA helpers (baseline PTX, sm_80+) ----------------
__device__ __forceinline__ uint32_t smem_u32(const void* p) {
    uint32_t a;
    asm("{ .reg .u64 t; cvta.to.shared.u64 t, %1; cvt.u32.u64 %0, t; }" : "=r"(a) : "l"(p));
    return a;
}
#define LDSM_X4(r0, r1, r2, r3, addr) \
    asm volatile("ldmatrix.sync.aligned.m8n8.x4.shared.b16 {%0,%1,%2,%3}, [%4];" \
        : "=r"(r0), "=r"(r1), "=r"(r2), "=r"(r3) : "r"(addr))

// not volatile — pure register computation, lets the compiler interleave chains.
__device__ __forceinline__ void mma_bf16(float c[4], const uint32_t a[4],
                                         uint32_t b0, uint32_t b1) {
    asm("mma.sync.aligned.m16n8k16.row.col.f32.bf16.bf16.f32 "
        "{%0,%1,%2,%3}, {%4,%5,%6,%7}, {%8,%9}, {%0,%1,%2,%3};"
        : "+f"(c[0]), "+f"(c[1]), "+f"(c[2]), "+f"(c[3])
        : "r"(a[0]), "r"(a[1]), "r"(a[2]), "r"(a[3]), "r"(b0), "r"(b1));
}

#define CP_ASYNC16(dst_u32, src_ptr) \
    asm volatile("cp.async.cg.shared.global [%0], [%1], 16;" \
        :: "r"(dst_u32), "l"(src_ptr) : "memory")
#define CP_COMMIT() asm volatile("cp.async.commit_group;" ::: "memory")
#define CP_WAIT0()  asm volatile("cp.async.wait_group 0;" ::: "memory")

// bf16 split helpers
__device__ __forceinline__ uint32_t pack_hi2(float a, float b, float& ra, float& rb) {
    __nv_bfloat162 h = __floats2bfloat162_rn(a, b);
    ra = a - __bfloat162float(h.x);
    rb = b - __bfloat162float(h.y);
    return *(uint32_t*)&h;
}
__device__ __forceinline__ uint32_t pack2(float a, float b) {
    __nv_bfloat162 h = __floats2bfloat162_rn(a, b);
    return *(uint32_t*)&h;
}

#define QSTR 136   // bf16 stride (272B): conflict-free ldmatrix

// ---------------------------------------------------------------------------
// Kernel 1: QKV projection via 3-chain bf16 HMMA.
// Grid (128, 3): CTA = 128 token rows x one 128-col slice (sel: 0=Q,1=K,2=V).
// X split hi/lo in SMEM; W slice transposed+split to [n][k]. Epilogue: bias
// (+Q scale), hi/lo split stores; V via SMEM fp32 transpose -> g_Vt[b][c][n].
// ---------------------------------------------------------------------------
#define XH_OFF 0
#define XL_OFF 34816
#define WH_OFF 69632
#define WL_OFF 104448
#define QKV_SMEM 139264

__global__ __launch_bounds__(256, 1)
void qkv_kernel(const float* __restrict__ x, const float* __restrict__ Wfc,
                const float* __restrict__ bfc, const float* __restrict__ scale) {
    extern __shared__ char sm[];
    const uint32_t sb = smem_u32(sm);
    const int tid = threadIdx.x, lane = tid & 31, w = tid >> 5;
    const int mbase = blockIdx.x * 128;
    const int sel = blockIdx.y;            // 0=Q, 1=K, 2=V
    const int cbase = sel * 128;

    const int bn  = (lane & 7) | ((lane & 16) >> 1);
    const int bk8 = (lane & 8);
    const int ar  = lane & 15;
    const int ac8 = (lane >> 4) << 3;

    __nv_bfloat16* WH = (__nv_bfloat16*)(sm + WH_OFF);
    __nv_bfloat16* WL = (__nv_bfloat16*)(sm + WL_OFF);

    // ---- X tile 128x128 fp32 -> bf16 hi/lo splits in SMEM ----
    // 128 rows x 32 float4/row = 4096 float4 -> 16 iterations of 256 threads.
    #pragma unroll
    for (int i = 0; i < 16; i++) {
        int idx = i * 256 + tid;
        int r = idx >> 5, c = (idx & 31) << 2;
        float4 v = *(const float4*)(x + (size_t)(mbase + r) * CDIM + c);
        float e0, e1;
        uint32_t h0 = pack_hi2(v.x, v.y, e0, e1);
        uint32_t l0 = pack2(e0, e1);
        uint32_t h1 = pack_hi2(v.z, v.w, e0, e1);
        uint32_t l1 = pack2(e0, e1);
        *(uint2*)(sm + XH_OFF + r * (QSTR * 2) + c * 2) = make_uint2(h0, h1);
        *(uint2*)(sm + XL_OFF + r * (QSTR * 2) + c * 2) = make_uint2(l0, l1);
    }
    // ---- W slice [k=128][n=128] -> WH/WL as [n][k] ----
    for (int idx = tid; idx < 128 * 128; idx += 256) {
        int k = idx >> 7, n = idx & 127;
        float wv = Wfc[k * 384 + cbase + n];
        __nv_bfloat16 hh = __float2bfloat16(wv);
        __nv_bfloat16 ll = __float2bfloat16(wv - __bfloat162float(hh));
        WH[n * QSTR + k] = hh;
        WL[n * QSTR + k] = ll;
    }
    __syncthreads();

    // ---- A fragments from XH/XL ----
    uint32_t xh[8][4], xl[8][4];
    #pragma unroll
    for (int kk = 0; kk < 8; kk++) {
        uint32_t a = sb + XH_OFF + ((w * 16 + ar) * QSTR + kk * 16 + ac8) * 2;
        LDSM_X4(xh[kk][0], xh[kk][1], xh[kk][2], xh[kk][3], a);
        uint32_t a2 = sb + XL_OFF + ((w * 16 + ar) * QSTR + kk * 16 + ac8) * 2;
        LDSM_X4(xl[kk][0], xl[kk][1], xl[kk][2], xl[kk][3], a2);
    }

    // ---- C = X @ Wslice (3 chains) ----
    float co[16][4];
    #pragma unroll
    for (int i = 0; i < 16; i++)
        #pragma unroll
        for (int j = 0; j < 4; j++) co[i][j] = 0.f;

    #pragma unroll
    for (int kk = 0; kk < 8; kk++) {
        #pragma unroll
        for (int nbp = 0; nbp < 8; nbp++) {
            uint32_t off = ((nbp * 16 + bn) * (QSTR * 2)) + (kk * 16 + bk8) * 2;
            uint32_t h0, h1, h2, h3, l0r, l1r, l2r, l3r;
            LDSM_X4(h0, h1, h2, h3, sb + WH_OFF + off);
            LDSM_X4(l0r, l1r, l2r, l3r, sb + WL_OFF + off);
            mma_bf16(co[2 * nbp],     xh[kk], h0, h1);
            mma_bf16(co[2 * nbp + 1], xh[kk], h2, h3);
            mma_bf16(co[2 * nbp],     xh[kk], l0r, l1r);
            mma_bf16(co[2 * nbp + 1], xh[kk], l2r, l3r);
            mma_bf16(co[2 * nbp],     xl[kk], h0, h1);
            mma_bf16(co[2 * nbp + 1], xl[kk], h2, h3);
        }
    }

    // ---- epilogue ----
    const int r0 = w * 16 + (lane >> 2);
    const int cb = (lane & 3) * 2;
    const float mul = (sel == 0) ? (1.0f / (sqrtf((float)CDIM) * scale[0])) : 1.0f;

    if (sel < 2) {
        __nv_bfloat16* bh = sel ? g_Kh : g_Qh;
        __nv_bfloat16* bl = sel ? g_Kl : g_Ql;
        #pragma unroll
        for (int nb = 0; nb < 16; nb++) {
            int col = nb * 8 + cb;
            float bx = bfc[cbase + col], by = bfc[cbase + col + 1];
            float a0 = (co[nb][0] + bx) * mul, a1 = (co[nb][1] + by) * mul;
            float a2 = (co[nb][2] + bx) * mul, a3 = (co[nb][3] + by) * mul;
            float e0, e1;
            uint32_t h01 = pack_hi2(a0, a1, e0, e1);
            uint32_t l01 = pack2(e0, e1);
            uint32_t h23 = pack_hi2(a2, a3, e0, e1);
            uint32_t l23 = pack2(e0, e1);
            size_t o0 = (size_t)(mbase + r0) * CDIM + col;
            size_t o1 = (size_t)(mbase + r0 + 8) * CDIM + col;
            *(uint32_t*)(bh + o0) = h01;
            *(uint32_t*)(bl + o0) = l01;
            *(uint32_t*)(bh + o1) = h23;
            *(uint32_t*)(bl + o1) = l23;
        }
    } else {
        // V: stage fp32 (with bias) to SMEM [128 tok][132], transpose, split-store
        float* T = (float*)sm;
        __syncthreads();   // all warps done with XH/XL/WH LDSM reads
        #pragma unroll
        for (int nb = 0; nb < 16; nb++) {
            int col = nb * 8 + cb;
            float bx = bfc[cbase + col], by = bfc[cbase + col + 1];
            T[r0 * 132 + col]           = co[nb][0] + bx;
            T[r0 * 132 + col + 1]       = co[nb][1] + by;
            T[(r0 + 8) * 132 + col]     = co[nb][2] + bx;
            T[(r0 + 8) * 132 + col + 1] = co[nb][3] + by;
        }
        __syncthreads();
        const int c = tid & 127, seg = tid >> 7;   // 2 segs x 64 tokens
        const int bb = mbase >> 12;
        size_t basea = ((size_t)(bb * CDIM + c)) * SEQ + (mbase & 4095) + seg * 64;
        uint32_t hw[32], lw[32];
        #pragma unroll
        for (int u = 0; u < 32; u++) {
            float v0 = T[(seg * 64 + 2 * u) * 132 + c];
            float v1 = T[(seg * 64 + 2 * u + 1) * 132 + c];
            float e0, e1;
            hw[u] = pack_hi2(v0, v1, e0, e1);
            lw[u] = pack2(e0, e1);
        }
        #pragma unroll
        for (int q = 0; q < 8; q++) {
            *(uint4*)(g_Vth + basea + 8 * q) =
                make_uint4(hw[4*q], hw[4*q+1], hw[4*q+2], hw[4*q+3]);
            *(uint4*)(g_Vtl + basea + 8 * q) =
                make_uint4(lw[4*q], lw[4*q+1], lw[4*q+2], lw[4*q+3]);
        }
    }
}

// ---------------------------------------------------------------------------
// Kernel 2: warp-MMA (HMMA) flash attention + fused output projection.
// Grid (32, 4) = 128 CTAs (one clean wave), 256 threads = 8 warps.
// cp.async double-buffered K/V; intra-tile pipelining: S(half0) -> exp0 ->
// S(half1) -> PV(kk0,1) -> exp1 -> PV(kk2,3) so MUFU bursts hide under MMAs.
// ---------------------------------------------------------------------------
#define VSTR 72    // bf16 stride (144B) for Vt tiles
#define OFF_KH 0
#define OFF_KL 17408
#define OFF_VH 34816
#define OFF_VL 53248
#define BUFSZ  71680
#define SM_TOT (2*BUFSZ)   // 143360

__device__ __forceinline__ void prefetch_tile(uint32_t sbuf, int b, int kr0, int tid) {
    #pragma unroll
    for (int i = 0; i < 4; i++) {
        int idx = i * 256 + tid;
        int r = idx >> 4, c = (idx & 15) << 3;
        size_t g = (size_t)(b * SEQ + kr0 + r) * CDIM + c;
        CP_ASYNC16(sbuf + OFF_KH + r * (QSTR * 2) + c * 2, g_Kh + g);
        CP_ASYNC16(sbuf + OFF_KL + r * (QSTR * 2) + c * 2, g_Kl + g);
    }
    #pragma unroll
    for (int i = 0; i < 4; i++) {
        int idx = i * 256 + tid;
        int r = idx >> 3, j8 = (idx & 7) << 3;
        size_t g = (size_t)(b * CDIM + r) * SEQ + kr0 + j8;
        CP_ASYNC16(sbuf + OFF_VH + r * (VSTR * 2) + j8 * 2, g_Vth + g);
        CP_ASYNC16(sbuf + OFF_VL + r * (VSTR * 2) + j8 * 2, g_Vtl + g);
    }
    CP_COMMIT();
}

__global__ __launch_bounds__(256, 1)
void attn_kernel(const float* __restrict__ Wout, const float* __restrict__ bout,
                 float* __restrict__ out) {
    extern __shared__ char smem8[];
    const uint32_t sb = smem_u32(smem8);
    const int tid = threadIdx.x, lane = tid & 31, w = tid >> 5;
    const int b = blockIdx.y;
    const int qr0 = blockIdx.x * 128;

    const int bn  = (lane & 7) | ((lane & 16) >> 1);
    const int bk8 = (lane & 8);
    const int ar  = lane & 15;
    const int ac8 = (lane >> 4) << 3;

    // ---- kick off prefetch of tile 0 into buffer 0 ----
    prefetch_tile(sb, b, 0, tid);

    // ---- stage Qh then Ql through buffer-1 region, load A fragments ----
    uint32_t qh[8][4], ql[8][4];
    {
        __nv_bfloat16* Qs = (__nv_bfloat16*)(smem8 + BUFSZ);
        const uint32_t qsb = sb + BUFSZ;
        #pragma unroll
        for (int i = 0; i < 8; i++) {
            int idx = i * 256 + tid;
            int r = idx >> 4, c = (idx & 15) << 3;
            *(uint4*)(Qs + r * QSTR + c) =
                *(const uint4*)(g_Qh + (size_t)(b * SEQ + qr0 + r) * CDIM + c);
        }
        __syncthreads();
        #pragma unroll
        for (int kk = 0; kk < 8; kk++) {
            uint32_t a = qsb + ((w * 16 + ar) * QSTR + kk * 16 + ac8) * 2;
            LDSM_X4(qh[kk][0], qh[kk][1], qh[kk][2], qh[kk][3], a);
        }
        __syncthreads();
        #pragma unroll
        for (int i = 0; i < 8; i++) {
            int idx = i * 256 + tid;
            int r = idx >> 4, c = (idx & 15) << 3;
            *(uint4*)(Qs + r * QSTR + c) =
                *(const uint4*)(g_Ql + (size_t)(b * SEQ + qr0 + r) * CDIM + c);
        }
        __syncthreads();
        #pragma unroll
        for (int kk = 0; kk < 8; kk++) {
            uint32_t a = qsb + ((w * 16 + ar) * QSTR + kk * 16 + ac8) * 2;
            LDSM_X4(ql[kk][0], ql[kk][1], ql[kk][2], ql[kk][3], a);
        }
    }

    float co[16][4];
    #pragma unroll
    for (int i = 0; i < 16; i++)
        #pragma unroll
        for (int j = 0; j < 4; j++) co[i][j] = 0.f;
    float l0 = 0.f, l1 = 0.f;

    CP_WAIT0();
    __syncthreads();

    for (int t = 0; t < NTILES; t++) {
        const uint32_t sbuf = sb + (t & 1) * BUFSZ;

        if (t + 1 < NTILES)
            prefetch_tile(sb + ((t + 1) & 1) * BUFSZ, b, (t + 1) * KVT, tid);

        float cs[8][4];
        #pragma unroll
        for (int i = 0; i < 8; i++)
            #pragma unroll
            for (int j = 0; j < 4; j++) cs[i][j] = 0.f;

        uint32_t pah[4][4], pal[4][4];

        // ---- S half A: KV cols 0-31 (nbp 0,1) ----
        #pragma unroll
        for (int kk = 0; kk < 8; kk++) {
            #pragma unroll
            for (int nbp = 0; nbp < 2; nbp++) {
                uint32_t off = ((nbp * 16 + bn) * (QSTR * 2)) + (kk * 16 + bk8) * 2;
                uint32_t h0, h1, h2, h3, l0r, l1r, l2r, l3r;
                LDSM_X4(h0, h1, h2, h3, sbuf + OFF_KH + off);
                LDSM_X4(l0r, l1r, l2r, l3r, sbuf + OFF_KL + off);
                mma_bf16(cs[2 * nbp],     qh[kk], h0, h1);
                mma_bf16(cs[2 * nbp + 1], qh[kk], h2, h3);
                mma_bf16(cs[2 * nbp],     qh[kk], l0r, l1r);
                mma_bf16(cs[2 * nbp + 1], qh[kk], l2r, l3r);
                mma_bf16(cs[2 * nbp],     ql[kk], h0, h1);
                mma_bf16(cs[2 * nbp + 1], ql[kk], h2, h3);
            }
        }
        // ---- exp/pack half A ----
        #pragma unroll
        for (int nb = 0; nb < 4; nb++) {
            cs[nb][0] = __expf(cs[nb][0]);
            cs[nb][1] = __expf(cs[nb][1]);
            cs[nb][2] = __expf(cs[nb][2]);
            cs[nb][3] = __expf(cs[nb][3]);
            l0 += cs[nb][0] + cs[nb][1];
            l1 += cs[nb][2] + cs[nb][3];
        }
        #pragma unroll
        for (int j = 0; j < 2; j++) {
            float e0, e1;
            pah[j][0] = pack_hi2(cs[2*j][0],   cs[2*j][1],   e0, e1); pal[j][0] = pack2(e0, e1);
            pah[j][1] = pack_hi2(cs[2*j][2],   cs[2*j][3],   e0, e1); pal[j][1] = pack2(e0, e1);
            pah[j][2] = pack_hi2(cs[2*j+1][0], cs[2*j+1][1], e0, e1); pal[j][2] = pack2(e0, e1);
            pah[j][3] = pack_hi2(cs[2*j+1][2], cs[2*j+1][3], e0, e1); pal[j][3] = pack2(e0, e1);
        }
        // ---- S half B: KV cols 32-63 (nbp 2,3) — covers exp-A latency ----
        #pragma unroll
        for (int kk = 0; kk < 8; kk++) {
            #pragma unroll
            for (int nbp = 2; nbp < 4; nbp++) {
                uint32_t off = ((nbp * 16 + bn) * (QSTR * 2)) + (kk * 16 + bk8) * 2;
                uint32_t h0, h1, h2, h3, l0r, l1r, l2r, l3r;
                LDSM_X4(h0, h1, h2, h3, sbuf + OFF_KH + off);
                LDSM_X4(l0r, l1r, l2r, l3r, sbuf + OFF_KL + off);
                mma_bf16(cs[2 * nbp],     qh[kk], h0, h1);
                mma_bf16(cs[2 * nbp + 1], qh[kk], h2, h3);
                mma_bf16(cs[2 * nbp],     qh[kk], l0r, l1r);
                mma_bf16(cs[2 * nbp + 1], qh[kk], l2r, l3r);
                mma_bf16(cs[2 * nbp],     ql[kk], h0, h1);
                mma_bf16(cs[2 * nbp + 1], ql[kk], h2, h3);
            }
        }
        // ---- PV part A: kv 0-31 (kk'=0,1) ----
        #pragma unroll
        for (int kk = 0; kk < 2; kk++) {
            #pragma unroll
            for (int nbp = 0; nbp < 8; nbp++) {
                uint32_t off = ((nbp * 16 + bn) * (VSTR * 2)) + (kk * 16 + bk8) * 2;
                uint32_t h0, h1, h2, h3, l0r, l1r, l2r, l3r;
                LDSM_X4(h0, h1, h2, h3, sbuf + OFF_VH + off);
                LDSM_X4(l0r, l1r, l2r, l3r, sbuf + OFF_VL + off);
                mma_bf16(co[2 * nbp],     pah[kk], h0, h1);
                mma_bf16(co[2 * nbp + 1], pah[kk], h2, h3);
                mma_bf16(co[2 * nbp],     pah[kk], l0r, l1r);
                mma_bf16(co[2 * nbp + 1], pah[kk], l2r, l3r);
                mma_bf16(co[2 * nbp],     pal[kk], h0, h1);
                mma_bf16(co[2 * nbp + 1], pal[kk], h2, h3);
            }
        }
        // ---- exp/pack half B — covers under PV-A MMAs ----
        #pragma unroll
        for (int nb = 4; nb < 8; nb++) {
            cs[nb][0] = __expf(cs[nb][0]);
            cs[nb][1] = __expf(cs[nb][1]);
            cs[nb][2] = __expf(cs[nb][2]);
            cs[nb][3] = __expf(cs[nb][3]);
            l0 += cs[nb][0] + cs[nb][1];
            l1 += cs[nb][2] + cs[nb][3];
        }
        #pragma unroll
        for (int j = 2; j < 4; j++) {
            float e0, e1;
            pah[j][0] = pack_hi2(cs[2*j][0],   cs[2*j][1],   e0, e1); pal[j][0] = pack2(e0, e1);
            pah[j][1] = pack_hi2(cs[2*j][2],   cs[2*j][3],   e0, e1); pal[j][1] = pack2(e0, e1);
            pah[j][2] = pack_hi2(cs[2*j+1][0], cs[2*j+1][1], e0, e1); pal[j][2] = pack2(e0, e1);
            pah[j][3] = pack_hi2(cs[2*j+1][2], cs[2*j+1][3], e0, e1); pal[j][3] = pack2(e0, e1);
        }
        // ---- PV part B: kv 32-63 (kk'=2,3) ----
        #pragma unroll
        for (int kk = 2; kk < 4; kk++) {
            #pragma unroll
            for (int nbp = 0; nbp < 8; nbp++) {
                uint32_t off = ((nbp * 16 + bn) * (VSTR * 2)) + (kk * 16 + bk8) * 2;
                uint32_t h0, h1, h2, h3, l0r, l1r, l2r, l3r;
                LDSM_X4(h0, h1, h2, h3, sbuf + OFF_VH + off);
                LDSM_X4(l0r, l1r, l2r, l3r, sbuf + OFF_VL + off);
                mma_bf16(co[2 * nbp],     pah[kk], h0, h1);
                mma_bf16(co[2 * nbp + 1], pah[kk], h2, h3);
                mma_bf16(co[2 * nbp],     pah[kk], l0r, l1r);
                mma_bf16(co[2 * nbp + 1], pah[kk], l2r, l3r);
                mma_bf16(co[2 * nbp],     pal[kk], h0, h1);
                mma_bf16(co[2 * nbp + 1], pal[kk], h2, h3);
            }
        }

        CP_WAIT0();
        __syncthreads();
    }

    // ---- finalize l, normalize O ----
    l0 += __shfl_xor_sync(0xffffffffu, l0, 1);
    l0 += __shfl_xor_sync(0xffffffffu, l0, 2);
    l1 += __shfl_xor_sync(0xffffffffu, l1, 1);
    l1 += __shfl_xor_sync(0xffffffffu, l1, 2);
    const float inv0 = 1.0f / l0, inv1 = 1.0f / l1;
    #pragma unroll
    for (int nb = 0; nb < 16; nb++) {
        co[nb][0] *= inv0; co[nb][1] *= inv0;
        co[nb][2] *= inv1; co[nb][3] *= inv1;
    }

    // ---- W_out^T hi/lo -> SMEM (reuse buffer 0) ----
    {
        __nv_bfloat16* Wh = (__nv_bfloat16*)smem8;
        __nv_bfloat16* Wl = (__nv_bfloat16*)(smem8 + OFF_VH);
        for (int idx = tid; idx < CDIM * CDIM; idx += 256) {
            int cin = idx >> 7, cout = idx & 127;
            float wv = Wout[idx];
            __nv_bfloat16 hh = __float2bfloat16(wv);
            __nv_bfloat16 ll = __float2bfloat16(wv - __bfloat162float(hh));
            Wh[cout * QSTR + cin] = hh;
            Wl[cout * QSTR + cin] = ll;
        }
    }

    // ---- O -> A fragments (hi/lo) ----
    uint32_t oah[8][4], oal[8][4];
    #pragma unroll
    for (int j = 0; j < 8; j++) {
        float e0, e1;
        oah[j][0] = pack_hi2(co[2*j][0],   co[2*j][1],   e0, e1); oal[j][0] = pack2(e0, e1);
        oah[j][1] = pack_hi2(co[2*j][2],   co[2*j][3],   e0, e1); oal[j][1] = pack2(e0, e1);
        oah[j][2] = pack_hi2(co[2*j+1][0], co[2*j+1][1], e0, e1); oal[j][2] = pack2(e0, e1);
        oah[j][3] = pack_hi2(co[2*j+1][2], co[2*j+1][3], e0, e1); oal[j][3] = pack2(e0, e1);
    }
    __syncthreads();

    // ---- D = O @ W_out (3 chains) ----
    #pragma unroll
    for (int i = 0; i < 16; i++)
        #pragma unroll
        for (int j = 0; j < 4; j++) co[i][j] = 0.f;

    #pragma unroll
    for (int kk = 0; kk < 8; kk++) {
        #pragma unroll
        for (int nbp = 0; nbp < 8; nbp++) {
            uint32_t off = ((nbp * 16 + bn) * (QSTR * 2)) + (kk * 16 + bk8) * 2;
            uint32_t h0, h1, h2, h3, l0r, l1r, l2r, l3r;
            LDSM_X4(h0, h1, h2, h3, sb + off);
            LDSM_X4(l0r, l1r, l2r, l3r, sb + OFF_VH + off);
            mma_bf16(co[2 * nbp],     oah[kk], h0, h1);
            mma_bf16(co[2 * nbp + 1], oah[kk], h2, h3);
            mma_bf16(co[2 * nbp],     oah[kk], l0r, l1r);
            mma_bf16(co[2 * nbp + 1], oah[kk], l2r, l3r);
            mma_bf16(co[2 * nbp],     oal[kk], h0, h1);
            mma_bf16(co[2 * nbp + 1], oal[kk], h2, h3);
        }
    }

    // ---- + bias, store ----
    {
        const int r0g = qr0 + w * 16 + (lane >> 2);
        const int cb = (lane & 3) * 2;
        float* base0 = out + (size_t)(b * SEQ + r0g) * CDIM;
        float* base1 = base0 + 8 * CDIM;
        #pragma unroll
        for (int nb = 0; nb < 16; nb++) {
            int col = nb * 8 + cb;
            float bx = bout[col], by = bout[col + 1];
            float2 v0 = make_float2(co[nb][0] + bx, co[nb][1] + by);
            float2 v1 = make_float2(co[nb][2] + bx, co[nb][3] + by);
            *(float2*)(base0 + col) = v0;
            *(float2*)(base1 + col) = v1;
        }
    }
}

// ---------------------------------------------------------------------------
extern "C" void kernel_launch(void* const* d_in, const int* in_sizes, int n_in,
                              void* d_out, int out_size) {
    const float* x    = (const float*)d_in[0];
    const float* Wfc  = (const float*)d_in[1];
    const float* bfc  = (const float*)d_in[2];
    const float* Wout = (const float*)d_in[3];
    const float* bo   = (const float*)d_in[4];
    const float* sc   = (const float*)d_in[5];
    float* out = (float*)d_out;

    cudaFuncSetAttribute(qkv_kernel, cudaFuncAttributeMaxDynamicSharedMemorySize, QKV_SMEM);
    cudaFuncSetAttribute(attn_kernel, cudaFuncAttributeMaxDynamicSharedMemorySize, SM_TOT);

    qkv_kernel<<<dim3(128, 3), 256, QKV_SMEM>>>(x, Wfc, bfc, sc);
    attn_kernel<<<dim3(32, 4), 256, SM_TOT>>>(Wout, bo, out);
}

// round 11
// speedup vs baseline: 1.1688x; 1.0073x over previous
#include <cuda_runtime.h>
#include <cuda_bf16.h>
#include <math.h>
#include <stdint.h>

#define BATCH 4
#define SEQ   4096
#define CDIM  128
#define MTOT  (BATCH*SEQ)
#define KVT   64
#define NTILES (SEQ/KVT)

// bf16 hi/lo split operands (scale folded into Q). V stored TRANSPOSED per batch: [b][c][n].
__device__ __nv_bfloat16 g_Qh[MTOT*CDIM], g_Ql[MTOT*CDIM];
__device__ __nv_bfloat16 g_Kh[MTOT*CDIM], g_Kl[MTOT*CDIM];
__device__ __nv_bfloat16 g_Vth[MTOT*CDIM], g_Vtl[MTOT*CDIM];

// ---------------- warp-MMA helpers (baseline PTX, sm_80+) ----------------
__device__ __forceinline__ uint32_t smem_u32(const void* p) {
    uint32_t a;
    asm("{ .reg .u64 t; cvta.to.shared.u64 t, %1; cvt.u32.u64 %0, t; }" : "=r"(a) : "l"(p));
    return a;
}
#define LDSM_X4(r0, r1, r2, r3, addr) \
    asm volatile("ldmatrix.sync.aligned.m8n8.x4.shared.b16 {%0,%1,%2,%3}, [%4];" \
        : "=r"(r0), "=r"(r1), "=r"(r2), "=r"(r3) : "r"(addr))

// not volatile — pure register computation, lets the compiler interleave chains.
__device__ __forceinline__ void mma_bf16(float c[4], const uint32_t a[4],
                                         uint32_t b0, uint32_t b1) {
    asm("mma.sync.aligned.m16n8k16.row.col.f32.bf16.bf16.f32 "
        "{%0,%1,%2,%3}, {%4,%5,%6,%7}, {%8,%9}, {%0,%1,%2,%3};"
        : "+f"(c[0]), "+f"(c[1]), "+f"(c[2]), "+f"(c[3])
        : "r"(a[0]), "r"(a[1]), "r"(a[2]), "r"(a[3]), "r"(b0), "r"(b1));
}

#define CP_ASYNC16(dst_u32, src_ptr) \
    asm volatile("cp.async.cg.shared.global [%0], [%1], 16;" \
        :: "r"(dst_u32), "l"(src_ptr) : "memory")
#define CP_COMMIT() asm volatile("cp.async.commit_group;" ::: "memory")
#define CP_WAIT0()  asm volatile("cp.async.wait_group 0;" ::: "memory")

// bf16 split helpers
__device__ __forceinline__ uint32_t pack_hi2(float a, float b, float& ra, float& rb) {
    __nv_bfloat162 h = __floats2bfloat162_rn(a, b);
    ra = a - __bfloat162float(h.x);
    rb = b - __bfloat162float(h.y);
    return *(uint32_t*)&h;
}
__device__ __forceinline__ uint32_t pack2(float a, float b) {
    __nv_bfloat162 h = __floats2bfloat162_rn(a, b);
    return *(uint32_t*)&h;
}

#define QSTR 136   // bf16 stride (272B): conflict-free ldmatrix

// ---------------------------------------------------------------------------
// Kernel 1: fused QKV projection via 3-chain bf16 HMMA — ONE WAVE.
// Grid 128: CTA = 128 token rows; loops sel=0..2 (Q,K,V slices) reusing the
// X tile (loaded+split once, A-fragments in registers once).
// Epilogue: bias (+Q scale), hi/lo split stores; V via SMEM fp32 transpose
// (reuses the X region after V MMAs) -> g_Vt[b][c][n].
// ---------------------------------------------------------------------------
#define XH_OFF 0
#define XL_OFF 34816
#define WH_OFF 69632
#define WL_OFF 104448
#define QKV_SMEM 139264

__global__ __launch_bounds__(256, 1)
void qkv_kernel(const float* __restrict__ x, const float* __restrict__ Wfc,
                const float* __restrict__ bfc, const float* __restrict__ scale) {
    extern __shared__ char sm[];
    const uint32_t sb = smem_u32(sm);
    const int tid = threadIdx.x, lane = tid & 31, w = tid >> 5;
    const int mbase = blockIdx.x * 128;

    const int bn  = (lane & 7) | ((lane & 16) >> 1);
    const int bk8 = (lane & 8);
    const int ar  = lane & 15;
    const int ac8 = (lane >> 4) << 3;

    __nv_bfloat16* WH = (__nv_bfloat16*)(sm + WH_OFF);
    __nv_bfloat16* WL = (__nv_bfloat16*)(sm + WL_OFF);

    // ---- X tile 128x128 fp32 -> bf16 hi/lo splits in SMEM (ONCE) ----
    // 128 rows x 32 float4/row = 4096 float4 -> 16 iterations of 256 threads.
    #pragma unroll
    for (int i = 0; i < 16; i++) {
        int idx = i * 256 + tid;
        int r = idx >> 5, c = (idx & 31) << 2;
        float4 v = *(const float4*)(x + (size_t)(mbase + r) * CDIM + c);
        float e0, e1;
        uint32_t h0 = pack_hi2(v.x, v.y, e0, e1);
        uint32_t l0 = pack2(e0, e1);
        uint32_t h1 = pack_hi2(v.z, v.w, e0, e1);
        uint32_t l1 = pack2(e0, e1);
        *(uint2*)(sm + XH_OFF + r * (QSTR * 2) + c * 2) = make_uint2(h0, h1);
        *(uint2*)(sm + XL_OFF + r * (QSTR * 2) + c * 2) = make_uint2(l0, l1);
    }
    __syncthreads();

    // ---- X A-fragments (ONCE, reused for all 3 slices) ----
    uint32_t xh[8][4], xl[8][4];
    #pragma unroll
    for (int kk = 0; kk < 8; kk++) {
        uint32_t a = sb + XH_OFF + ((w * 16 + ar) * QSTR + kk * 16 + ac8) * 2;
        LDSM_X4(xh[kk][0], xh[kk][1], xh[kk][2], xh[kk][3], a);
        uint32_t a2 = sb + XL_OFF + ((w * 16 + ar) * QSTR + kk * 16 + ac8) * 2;
        LDSM_X4(xl[kk][0], xl[kk][1], xl[kk][2], xl[kk][3], a2);
    }

    const int r0 = w * 16 + (lane >> 2);
    const int cb = (lane & 3) * 2;

    for (int sel = 0; sel < 3; sel++) {
        const int cbase = sel * 128;

        // ---- W slice [k=128][n=128] -> WH/WL as [n][k] ----
        for (int idx = tid; idx < 128 * 128; idx += 256) {
            int k = idx >> 7, n = idx & 127;
            float wv = Wfc[k * 384 + cbase + n];
            __nv_bfloat16 hh = __float2bfloat16(wv);
            __nv_bfloat16 ll = __float2bfloat16(wv - __bfloat162float(hh));
            WH[n * QSTR + k] = hh;
            WL[n * QSTR + k] = ll;
        }
        __syncthreads();

        // ---- C = X @ Wslice (3 chains) ----
        float co[16][4];
        #pragma unroll
        for (int i = 0; i < 16; i++)
            #pragma unroll
            for (int j = 0; j < 4; j++) co[i][j] = 0.f;

        #pragma unroll
        for (int kk = 0; kk < 8; kk++) {
            #pragma unroll
            for (int nbp = 0; nbp < 8; nbp++) {
                uint32_t off = ((nbp * 16 + bn) * (QSTR * 2)) + (kk * 16 + bk8) * 2;
                uint32_t h0, h1, h2, h3, l0r, l1r, l2r, l3r;
                LDSM_X4(h0, h1, h2, h3, sb + WH_OFF + off);
                LDSM_X4(l0r, l1r, l2r, l3r, sb + WL_OFF + off);
                mma_bf16(co[2 * nbp],     xh[kk], h0, h1);
                mma_bf16(co[2 * nbp + 1], xh[kk], h2, h3);
                mma_bf16(co[2 * nbp],     xh[kk], l0r, l1r);
                mma_bf16(co[2 * nbp + 1], xh[kk], l2r, l3r);
                mma_bf16(co[2 * nbp],     xl[kk], h0, h1);
                mma_bf16(co[2 * nbp + 1], xl[kk], h2, h3);
            }
        }

        // ---- epilogue ----
        if (sel < 2) {
            const float mul = (sel == 0) ? (1.0f / (sqrtf((float)CDIM) * scale[0])) : 1.0f;
            __nv_bfloat16* bh = sel ? g_Kh : g_Qh;
            __nv_bfloat16* bl = sel ? g_Kl : g_Ql;
            #pragma unroll
            for (int nb = 0; nb < 16; nb++) {
                int col = nb * 8 + cb;
                float bx = bfc[cbase + col], by = bfc[cbase + col + 1];
                float a0 = (co[nb][0] + bx) * mul, a1 = (co[nb][1] + by) * mul;
                float a2 = (co[nb][2] + bx) * mul, a3 = (co[nb][3] + by) * mul;
                float e0, e1;
                uint32_t h01 = pack_hi2(a0, a1, e0, e1);
                uint32_t l01 = pack2(e0, e1);
                uint32_t h23 = pack_hi2(a2, a3, e0, e1);
                uint32_t l23 = pack2(e0, e1);
                size_t o0 = (size_t)(mbase + r0) * CDIM + col;
                size_t o1 = (size_t)(mbase + r0 + 8) * CDIM + col;
                *(uint32_t*)(bh + o0) = h01;
                *(uint32_t*)(bl + o0) = l01;
                *(uint32_t*)(bh + o1) = h23;
                *(uint32_t*)(bl + o1) = l23;
            }
            __syncthreads();   // co stores done before next sel overwrites WH/WL
        } else {
            // V: stage fp32 (+bias) into X region [128 tok][132], transpose, split-store
            float* T = (float*)sm;
            __syncthreads();   // all warps done with XH/XL/WH/WL LDSM reads
            #pragma unroll
            for (int nb = 0; nb < 16; nb++) {
                int col = nb * 8 + cb;
                float bx = bfc[cbase + col], by = bfc[cbase + col + 1];
                T[r0 * 132 + col]           = co[nb][0] + bx;
                T[r0 * 132 + col + 1]       = co[nb][1] + by;
                T[(r0 + 8) * 132 + col]     = co[nb][2] + bx;
                T[(r0 + 8) * 132 + col + 1] = co[nb][3] + by;
            }
            __syncthreads();
            const int c = tid & 127, seg = tid >> 7;   // 2 segs x 64 tokens
            const int bb = mbase >> 12;
            size_t basea = ((size_t)(bb * CDIM + c)) * SEQ + (mbase & 4095) + seg * 64;
            uint32_t hw[32], lw[32];
            #pragma unroll
            for (int u = 0; u < 32; u++) {
                float v0 = T[(seg * 64 + 2 * u) * 132 + c];
                float v1 = T[(seg * 64 + 2 * u + 1) * 132 + c];
                float e0, e1;
                hw[u] = pack_hi2(v0, v1, e0, e1);
                lw[u] = pack2(e0, e1);
            }
            #pragma unroll
            for (int q = 0; q < 8; q++) {
                *(uint4*)(g_Vth + basea + 8 * q) =
                    make_uint4(hw[4*q], hw[4*q+1], hw[4*q+2], hw[4*q+3]);
                *(uint4*)(g_Vtl + basea + 8 * q) =
                    make_uint4(lw[4*q], lw[4*q+1], lw[4*q+2], lw[4*q+3]);
            }
        }
    }
}

// ---------------------------------------------------------------------------
// Kernel 2: warp-MMA (HMMA) flash attention + fused output projection.
// Grid (32, 4) = 128 CTAs (one clean wave), 256 threads = 8 warps.
// cp.async double-buffered K/V; intra-tile pipelining of S/exp/PV.
// ---------------------------------------------------------------------------
#define VSTR 72    // bf16 stride (144B) for Vt tiles
#define OFF_KH 0
#define OFF_KL 17408
#define OFF_VH 34816
#define OFF_VL 53248
#define BUFSZ  71680
#define SM_TOT (2*BUFSZ)   // 143360

__device__ __forceinline__ void prefetch_tile(uint32_t sbuf, int b, int kr0, int tid) {
    #pragma unroll
    for (int i = 0; i < 4; i++) {
        int idx = i * 256 + tid;
        int r = idx >> 4, c = (idx & 15) << 3;
        size_t g = (size_t)(b * SEQ + kr0 + r) * CDIM + c;
        CP_ASYNC16(sbuf + OFF_KH + r * (QSTR * 2) + c * 2, g_Kh + g);
        CP_ASYNC16(sbuf + OFF_KL + r * (QSTR * 2) + c * 2, g_Kl + g);
    }
    #pragma unroll
    for (int i = 0; i < 4; i++) {
        int idx = i * 256 + tid;
        int r = idx >> 3, j8 = (idx & 7) << 3;
        size_t g = (size_t)(b * CDIM + r) * SEQ + kr0 + j8;
        CP_ASYNC16(sbuf + OFF_VH + r * (VSTR * 2) + j8 * 2, g_Vth + g);
        CP_ASYNC16(sbuf + OFF_VL + r * (VSTR * 2) + j8 * 2, g_Vtl + g);
    }
    CP_COMMIT();
}

__global__ __launch_bounds__(256, 1)
void attn_kernel(const float* __restrict__ Wout, const float* __restrict__ bout,
                 float* __restrict__ out) {
    extern __shared__ char smem8[];
    const uint32_t sb = smem_u32(smem8);
    const int tid = threadIdx.x, lane = tid & 31, w = tid >> 5;
    const int b = blockIdx.y;
    const int qr0 = blockIdx.x * 128;

    const int bn  = (lane & 7) | ((lane & 16) >> 1);
    const int bk8 = (lane & 8);
    const int ar  = lane & 15;
    const int ac8 = (lane >> 4) << 3;

    // ---- kick off prefetch of tile 0 into buffer 0 ----
    prefetch_tile(sb, b, 0, tid);

    // ---- stage Qh and Ql concurrently into buffer-1 halves; ONE sync ----
    uint32_t qh[8][4], ql[8][4];
    {
        __nv_bfloat16* Qh = (__nv_bfloat16*)(smem8 + BUFSZ);
        __nv_bfloat16* Ql = (__nv_bfloat16*)(smem8 + BUFSZ + 34816);
        #pragma unroll
        for (int i = 0; i < 8; i++) {
            int idx = i * 256 + tid;
            int r = idx >> 4, c = (idx & 15) << 3;
            size_t g = (size_t)(b * SEQ + qr0 + r) * CDIM + c;
            *(uint4*)(Qh + r * QSTR + c) = *(const uint4*)(g_Qh + g);
            *(uint4*)(Ql + r * QSTR + c) = *(const uint4*)(g_Ql + g);
        }
        __syncthreads();
        #pragma unroll
        for (int kk = 0; kk < 8; kk++) {
            uint32_t a = sb + BUFSZ + ((w * 16 + ar) * QSTR + kk * 16 + ac8) * 2;
            LDSM_X4(qh[kk][0], qh[kk][1], qh[kk][2], qh[kk][3], a);
            uint32_t a2 = a + 34816;
            LDSM_X4(ql[kk][0], ql[kk][1], ql[kk][2], ql[kk][3], a2);
        }
    }

    float co[16][4];
    #pragma unroll
    for (int i = 0; i < 16; i++)
        #pragma unroll
        for (int j = 0; j < 4; j++) co[i][j] = 0.f;
    float l0 = 0.f, l1 = 0.f;

    CP_WAIT0();
    __syncthreads();

    for (int t = 0; t < NTILES; t++) {
        const uint32_t sbuf = sb + (t & 1) * BUFSZ;

        if (t + 1 < NTILES)
            prefetch_tile(sb + ((t + 1) & 1) * BUFSZ, b, (t + 1) * KVT, tid);

        float cs[8][4];
        #pragma unroll
        for (int i = 0; i < 8; i++)
            #pragma unroll
            for (int j = 0; j < 4; j++) cs[i][j] = 0.f;

        uint32_t pah[4][4], pal[4][4];

        // ---- S half A: KV cols 0-31 (nbp 0,1) ----
        #pragma unroll
        for (int kk = 0; kk < 8; kk++) {
            #pragma unroll
            for (int nbp = 0; nbp < 2; nbp++) {
                uint32_t off = ((nbp * 16 + bn) * (QSTR * 2)) + (kk * 16 + bk8) * 2;
                uint32_t h0, h1, h2, h3, l0r, l1r, l2r, l3r;
                LDSM_X4(h0, h1, h2, h3, sbuf + OFF_KH + off);
                LDSM_X4(l0r, l1r, l2r, l3r, sbuf + OFF_KL + off);
                mma_bf16(cs[2 * nbp],     qh[kk], h0, h1);
                mma_bf16(cs[2 * nbp + 1], qh[kk], h2, h3);
                mma_bf16(cs[2 * nbp],     qh[kk], l0r, l1r);
                mma_bf16(cs[2 * nbp + 1], qh[kk], l2r, l3r);
                mma_bf16(cs[2 * nbp],     ql[kk], h0, h1);
                mma_bf16(cs[2 * nbp + 1], ql[kk], h2, h3);
            }
        }
        // ---- exp/pack half A ----
        #pragma unroll
        for (int nb = 0; nb < 4; nb++) {
            cs[nb][0] = __expf(cs[nb][0]);
            cs[nb][1] = __expf(cs[nb][1]);
            cs[nb][2] = __expf(cs[nb][2]);
            cs[nb][3] = __expf(cs[nb][3]);
            l0 += cs[nb][0] + cs[nb][1];
            l1 += cs[nb][2] + cs[nb][3];
        }
        #pragma unroll
        for (int j = 0; j < 2; j++) {
            float e0, e1;
            pah[j][0] = pack_hi2(cs[2*j][0],   cs[2*j][1],   e0, e1); pal[j][0] = pack2(e0, e1);
            pah[j][1] = pack_hi2(cs[2*j][2],   cs[2*j][3],   e0, e1); pal[j][1] = pack2(e0, e1);
            pah[j][2] = pack_hi2(cs[2*j+1][0], cs[2*j+1][1], e0, e1); pal[j][2] = pack2(e0, e1);
            pah[j][3] = pack_hi2(cs[2*j+1][2], cs[2*j+1][3], e0, e1); pal[j][3] = pack2(e0, e1);
        }
        // ---- S half B: KV cols 32-63 (nbp 2,3) ----
        #pragma unroll
        for (int kk = 0; kk < 8; kk++) {
            #pragma unroll
            for (int nbp = 2; nbp < 4; nbp++) {
                uint32_t off = ((nbp * 16 + bn) * (QSTR * 2)) + (kk * 16 + bk8) * 2;
                uint32_t h0, h1, h2, h3, l0r, l1r, l2r, l3r;
                LDSM_X4(h0, h1, h2, h3, sbuf + OFF_KH + off);
                LDSM_X4(l0r, l1r, l2r, l3r, sbuf + OFF_KL + off);
                mma_bf16(cs[2 * nbp],     qh[kk], h0, h1);
                mma_bf16(cs[2 * nbp + 1], qh[kk], h2, h3);
                mma_bf16(cs[2 * nbp],     qh[kk], l0r, l1r);
                mma_bf16(cs[2 * nbp + 1], qh[kk], l2r, l3r);
                mma_bf16(cs[2 * nbp],     ql[kk], h0, h1);
                mma_bf16(cs[2 * nbp + 1], ql[kk], h2, h3);
            }
        }
        // ---- PV part A: kv 0-31 (kk'=0,1) ----
        #pragma unroll
        for (int kk = 0; kk < 2; kk++) {
            #pragma unroll
            for (int nbp = 0; nbp < 8; nbp++) {
                uint32_t off = ((nbp * 16 + bn) * (VSTR * 2)) + (kk * 16 + bk8) * 2;
                uint32_t h0, h1, h2, h3, l0r, l1r, l2r, l3r;
                LDSM_X4(h0, h1, h2, h3, sbuf + OFF_VH + off);
                LDSM_X4(l0r, l1r, l2r, l3r, sbuf + OFF_VL + off);
                mma_bf16(co[2 * nbp],     pah[kk], h0, h1);
                mma_bf16(co[2 * nbp + 1], pah[kk], h2, h3);
                mma_bf16(co[2 * nbp],     pah[kk], l0r, l1r);
                mma_bf16(co[2 * nbp + 1], pah[kk], l2r, l3r);
                mma_bf16(co[2 * nbp],     pal[kk], h0, h1);
                mma_bf16(co[2 * nbp + 1], pal[kk], h2, h3);
            }
        }
        // ---- exp/pack half B ----
        #pragma unroll
        for (int nb = 4; nb < 8; nb++) {
            cs[nb][0] = __expf(cs[nb][0]);
            cs[nb][1] = __expf(cs[nb][1]);
            cs[nb][2] = __expf(cs[nb][2]);
            cs[nb][3] = __expf(cs[nb][3]);
            l0 += cs[nb][0] + cs[nb][1];
            l1 += cs[nb][2] + cs[nb][3];
        }
        #pragma unroll
        for (int j = 2; j < 4; j++) {
            float e0, e1;
            pah[j][0] = pack_hi2(cs[2*j][0],   cs[2*j][1],   e0, e1); pal[j][0] = pack2(e0, e1);
            pah[j][1] = pack_hi2(cs[2*j][2],   cs[2*j][3],   e0, e1); pal[j][1] = pack2(e0, e1);
            pah[j][2] = pack_hi2(cs[2*j+1][0], cs[2*j+1][1], e0, e1); pal[j][2] = pack2(e0, e1);
            pah[j][3] = pack_hi2(cs[2*j+1][2], cs[2*j+1][3], e0, e1); pal[j][3] = pack2(e0, e1);
        }
        // ---- PV part B: kv 32-63 (kk'=2,3) ----
        #pragma unroll
        for (int kk = 2; kk < 4; kk++) {
            #pragma unroll
            for (int nbp = 0; nbp < 8; nbp++) {
                uint32_t off = ((nbp * 16 + bn) * (VSTR * 2)) + (kk * 16 + bk8) * 2;
                uint32_t h0, h1, h2, h3, l0r, l1r, l2r, l3r;
                LDSM_X4(h0, h1, h2, h3, sbuf + OFF_VH + off);
                LDSM_X4(l0r, l1r, l2r, l3r, sbuf + OFF_VL + off);
                mma_bf16(co[2 * nbp],     pah[kk], h0, h1);
                mma_bf16(co[2 * nbp + 1], pah[kk], h2, h3);
                mma_bf16(co[2 * nbp],     pah[kk], l0r, l1r);
                mma_bf16(co[2 * nbp + 1], pah[kk], l2r, l3r);
                mma_bf16(co[2 * nbp],     pal[kk], h0, h1);
                mma_bf16(co[2 * nbp + 1], pal[kk], h2, h3);
            }
        }

        CP_WAIT0();
        __syncthreads();
    }

    // ---- finalize l, normalize O ----
    l0 += __shfl_xor_sync(0xffffffffu, l0, 1);
    l0 += __shfl_xor_sync(0xffffffffu, l0, 2);
    l1 += __shfl_xor_sync(0xffffffffu, l1, 1);
    l1 += __shfl_xor_sync(0xffffffffu, l1, 2);
    const float inv0 = 1.0f / l0, inv1 = 1.0f / l1;
    #pragma unroll
    for (int nb = 0; nb < 16; nb++) {
        co[nb][0] *= inv0; co[nb][1] *= inv0;
        co[nb][2] *= inv1; co[nb][3] *= inv1;
    }

    // ---- W_out^T hi/lo -> SMEM (reuse buffer 0) ----
    {
        __nv_bfloat16* Wh = (__nv_bfloat16*)smem8;
        __nv_bfloat16* Wl = (__nv_bfloat16*)(smem8 + OFF_VH);
        for (int idx = tid; idx < CDIM * CDIM; idx += 256) {
            int cin = idx >> 7, cout = idx & 127;
            float wv = Wout[idx];
            __nv_bfloat16 hh = __float2bfloat16(wv);
            __nv_bfloat16 ll = __float2bfloat16(wv - __bfloat162float(hh));
            Wh[cout * QSTR + cin] = hh;
            Wl[cout * QSTR + cin] = ll;
        }
    }

    // ---- O -> A fragments (hi/lo) ----
    uint32_t oah[8][4], oal[8][4];
    #pragma unroll
    for (int j = 0; j < 8; j++) {
        float e0, e1;
        oah[j][0] = pack_hi2(co[2*j][0],   co[2*j][1],   e0, e1); oal[j][0] = pack2(e0, e1);
        oah[j][1] = pack_hi2(co[2*j][2],   co[2*j][3],   e0, e1); oal[j][1] = pack2(e0, e1);
        oah[j][2] = pack_hi2(co[2*j+1][0], co[2*j+1][1], e0, e1); oal[j][2] = pack2(e0, e1);
        oah[j][3] = pack_hi2(co[2*j+1][2], co[2*j+1][3], e0, e1); oal[j][3] = pack2(e0, e1);
    }
    __syncthreads();

    // ---- D = O @ W_out (3 chains) ----
    #pragma unroll
    for (int i = 0; i < 16; i++)
        #pragma unroll
        for (int j = 0; j < 4; j++) co[i][j] = 0.f;

    #pragma unroll
    for (int kk = 0; kk < 8; kk++) {
        #pragma unroll
        for (int nbp = 0; nbp < 8; nbp++) {
            uint32_t off = ((nbp * 16 + bn) * (QSTR * 2)) + (kk * 16 + bk8) * 2;
            uint32_t h0, h1, h2, h3, l0r, l1r, l2r, l3r;
            LDSM_X4(h0, h1, h2, h3, sb + off);
            LDSM_X4(l0r, l1r, l2r, l3r, sb + OFF_VH + off);
            mma_bf16(co[2 * nbp],     oah[kk], h0, h1);
            mma_bf16(co[2 * nbp + 1], oah[kk], h2, h3);
            mma_bf16(co[2 * nbp],     oah[kk], l0r, l1r);
            mma_bf16(co[2 * nbp + 1], oah[kk], l2r, l3r);
            mma_bf16(co[2 * nbp],     oal[kk], h0, h1);
            mma_bf16(co[2 * nbp + 1], oal[kk], h2, h3);
        }
    }

    // ---- + bias, store ----
    {
        const int r0g = qr0 + w * 16 + (lane >> 2);
        const int cb = (lane & 3) * 2;
        float* base0 = out + (size_t)(b * SEQ + r0g) * CDIM;
        float* base1 = base0 + 8 * CDIM;
        #pragma unroll
        for (int nb = 0; nb < 16; nb++) {
            int col = nb * 8 + cb;
            float bx = bout[col], by = bout[col + 1];
            float2 v0 = make_float2(co[nb][0] + bx, co[nb][1] + by);
            float2 v1 = make_float2(co[nb][2] + bx, co[nb][3] + by);
            *(float2*)(base0 + col) = v0;
            *(float2*)(base1 + col) = v1;
        }
    }
}

// ---------------------------------------------------------------------------
extern "C" void kernel_launch(void* const* d_in, const int* in_sizes, int n_in,
                              void* d_out, int out_size) {
    const float* x    = (const float*)d_in[0];
    const float* Wfc  = (const float*)d_in[1];
    const float* bfc  = (const float*)d_in[2];
    const float* Wout = (const float*)d_in[3];
    const float* bo   = (const float*)d_in[4];
    const float* sc   = (const float*)d_in[5];
    float* out = (float*)d_out;

    cudaFuncSetAttribute(qkv_kernel, cudaFuncAttributeMaxDynamicSharedMemorySize, QKV_SMEM);
    cudaFuncSetAttribute(attn_kernel, cudaFuncAttributeMaxDynamicSharedMemorySize, SM_TOT);

    qkv_kernel<<<128, 256, QKV_SMEM>>>(x, Wfc, bfc, sc);
    attn_kernel<<<dim3(32, 4), 256, SM_TOT>>>(Wout, bo, out);
}